// round 10
// baseline (speedup 1.0000x reference)
#include <cuda_runtime.h>
#include <cstdint>

#define CCH 32
#define DD 48
#define HHH 48
#define WWW 48
#define HW (HHH*WWW)           // 2304
#define DHW (DD*HHH*WWW)       // 110592
#define EPSf 1e-6f

#define TY 4                    // y-rows per block
#define TBLK 192                // 48 * TY voxels/threads per block
#define ZT 6                    // tile z extent  [z0-2, z0+3]
#define YT 9                    // tile y extent  [y0-2, y0+6]
#define TILE_N (ZT*YT*48)       // 2592 floats = 10368 B

// Pre-transposed mix weights: g_WT[m*32 + o] = w_mix[o*256 + m]
__device__ float g_WT[256 * 32];

__global__ void prep_WT_kernel(const float* __restrict__ w_mix) {
    int i = blockIdx.x * 256 + threadIdx.x;
    if (i < 256 * 32) {
        int m = i >> 5, o = i & 31;
        g_WT[m * 32 + o] = w_mix[o * 256 + m];
    }
}

// packed fp32x2 helpers
__device__ __forceinline__ void ffma2(unsigned long long &acc, unsigned long long w, unsigned long long v) {
    asm("fma.rn.f32x2 %0, %1, %2, %0;" : "+l"(acc) : "l"(w), "l"(v));
}
__device__ __forceinline__ unsigned long long pack2(float a) {
    unsigned long long r; asm("mov.b64 %0, {%1, %1};" : "=l"(r) : "f"(a)); return r;
}
__device__ __forceinline__ float2 unpack2(unsigned long long a) {
    float2 f; asm("mov.b64 {%0, %1}, %2;" : "=f"(f.x), "=f"(f.y) : "l"(a)); return f;
}

__device__ __forceinline__ float reflectf(float t, float size) {
    float c = fabsf(t + 0.5f);
    float m = fmodf(c, 2.0f * size);
    return fminf(m, 2.0f * size - m) - 0.5f;
}

// Dynamic shared layout (16B aligned blocks):
#define OFF_WT   0              // 256*32 floats = 32768 B
#define OFF_TILE 32768          // 2 * 2592 floats = 20736 B
#define OFF_WF   53504          // 12*32 floats = 1536 B
#define OFF_BF   55040          // 16 floats
#define OFF_BMIX 55104          // 32 floats
#define OFF_SG   55232          // 8 floats
#define SMEM_DYN 55264

__global__ __launch_bounds__(TBLK)
void geo_sample3d_kernel(const float* __restrict__ x,
                         const float* __restrict__ w_field,
                         const float* __restrict__ b_field,
                         const float* __restrict__ gates,
                         const float* __restrict__ b_mix,
                         float* __restrict__ out)
{
    extern __shared__ __align__(16) char dsm[];
    float* s_WT   = (float*)(dsm + OFF_WT);
    float* s_T    = (float*)(dsm + OFF_TILE);   // [2][TILE_N]
    float* s_wf   = (float*)(dsm + OFF_WF);
    float* s_bf   = (float*)(dsm + OFF_BF);
    float* s_bmix = (float*)(dsm + OFF_BMIX);
    float* s_sg   = (float*)(dsm + OFF_SG);

    const int tid = threadIdx.x;

    // block -> slab coords: n, z0, y0  (grid = 2 * 48 * 12)
    const int nb = blockIdx.x;
    const int n  = nb / (48 * 12);
    const int r  = nb - n * (48 * 12);
    const int z0 = r / 12;
    const int y0 = (r - z0 * 12) * TY;

    const int yloc = tid / 48;          // 0..3
    const int w    = tid - yloc * 48;   // 0..47
    const int y    = y0 + yloc;
    const int z    = z0;
    const int zyx  = z * HW + y * WWW + w;

    const float* __restrict__ xn = x + (size_t)n * CCH * DHW;

    // --- shared fills ---
    #pragma unroll 4
    for (int i = tid; i < 256 * 32; i += TBLK) s_WT[i] = g_WT[i];
    for (int i = tid; i < 12 * CCH; i += TBLK) s_wf[i] = w_field[i];
    if (tid < 12)  s_bf[tid]   = b_field[tid];
    if (tid < CCH) s_bmix[tid] = b_mix[tid];
    if (tid < 8)   s_sg[tid]   = 1.0f / (1.0f + expf(-gates[tid]));

    // --- start tile fill for channel 0 (overlaps phase 1/2 compute) ---
    {
        const float* __restrict__ bc = xn;   // channel 0
        for (int j = tid; j < TILE_N; j += TBLK) {
            int row = j / 48;
            int xx  = j - row * 48;
            int zt  = row / YT;
            int yt  = row - zt * YT;
            int zi  = min(max(z0 - 2 + zt, 0), DD - 1);
            int yi  = min(max(y0 - 2 + yt, 0), HHH - 1);
            s_T[j] = bc[zi * HW + yi * WWW + xx];
        }
    }

    // ---- Phase 1: field conv f[12] (global reads, L2/L1-resident) ----
    float f[12];
    {
        float bfl[12];
        #pragma unroll
        for (int o = 0; o < 12; o++) bfl[o] = b_field[o];   // tiny, cached
        #pragma unroll
        for (int o = 0; o < 12; o++) f[o] = bfl[o];
    }
    #pragma unroll 4
    for (int c = 0; c < CCH; c++) {
        float xc = xn[c * DHW + zyx];
        #pragma unroll
        for (int o = 0; o < 12; o++) f[o] = fmaf(w_field[o * CCH + c], xc, f[o]);
    }

    // ---- Phase 2: geometry + folded token coefficients ----
    int   tb[6], ox[6], oy[6], oz[6];
    float fx[6], fy[6], fz[6];
    float cA[3], cG[9], cLs[3];
    float sumIr2 = 0.0f;

    const float gx0 = (w + 0.5f) * (2.0f / WWW) - 1.0f;
    const float gy0 = (y + 0.5f) * (2.0f / HHH) - 1.0f;
    const float gz0 = (z + 0.5f) * (2.0f / DD)  - 1.0f;

    #pragma unroll
    for (int k = 0; k < 3; k++) {
        float vx = f[4*k+0], vy = f[4*k+1], vz = f[4*k+2], fr = f[4*k+3];
        float inv_norm = rsqrtf(vx*vx + vy*vy + vz*vz + EPSf);
        float ux = vx * inv_norm, uy = vy * inv_norm, uz = vz * inv_norm;
        float rr = 0.5f + 1.5f / (1.0f + expf(-fr));
        float dx = 2.0f * rr * ux / ((float)WWW + EPSf);
        float dy = 2.0f * rr * uy / ((float)HHH + EPSf);
        float dz = 2.0f * rr * uz / ((float)DD  + EPSf);
        float invr = 1.0f / (rr + EPSf);
        float ir2  = invr * invr;
        sumIr2 += ir2;

        float sg1 = 1.0f / (1.0f + expf(-gates[1+k]));
        cA[k] = 0.5f * sg1;

        #pragma unroll
        for (int s2 = 0; s2 < 2; s2++) {
            float sgn = s2 ? -1.0f : 1.0f;
            int   si  = 2*k + s2;
            float txu = ((gx0 + sgn*dx + 1.0f) * (float)WWW - 1.0f) * 0.5f;
            float tyu = ((gy0 + sgn*dy + 1.0f) * (float)HHH - 1.0f) * 0.5f;
            float tzu = ((gz0 + sgn*dz + 1.0f) * (float)DD  - 1.0f) * 0.5f;
            float ixs = reflectf(txu, (float)WWW);
            float iys = reflectf(tyu, (float)HHH);
            float izs = reflectf(tzu, (float)DD);

            float x0f = floorf(ixs), y0f = floorf(iys), z0f = floorf(izs);
            fx[si] = ixs - x0f;  fy[si] = iys - y0f;  fz[si] = izs - z0f;

            int x0i = (int)x0f; x0i = max(0, min(x0i, WWW-1)); int x1i = min(x0i+1, WWW-1);
            int y0i = (int)y0f; y0i = max(0, min(y0i, HHH-1)); int y1i = min(y0i+1, HHH-1);
            int z0i = (int)z0f; z0i = max(0, min(z0i, DD-1));  int z1i = min(z0i+1, DD-1);

            // tile-relative base offset (indices proven within tile bounds)
            tb[si] = (z0i - z0 + 2) * (YT*48) + (y0i - y0 + 2) * 48 + x0i;
            ox[si] = x1i - x0i;
            oy[si] = (y1i - y0i) * 48;
            oz[si] = (z1i - z0i) * (YT*48);
        }

        float ir05 = 0.5f * invr;
        cG[0*3+k] = ir05 * ux;   // gates folded after loop via s_sg (need smem ready)
        cG[1*3+k] = ir05 * uy;
        cG[2*3+k] = ir05 * uz;
        cLs[k]    = (1.0f/3.0f) * ir2;
    }

    __syncthreads();   // tile(ch0) + s_* tables ready

    // fold gates now that s_sg is visible
    #pragma unroll
    for (int k = 0; k < 3; k++) {
        cA[k]     *= 1.0f;               // already has sg
        cG[0*3+k] *= s_sg[4];
        cG[1*3+k] *= s_sg[5];
        cG[2*3+k] *= s_sg[6];
        cLs[k]    *= s_sg[7];
    }
    const float cLx = -s_sg[7] * (2.0f/3.0f) * sumIr2;
    const float cx  = s_sg[0];

    const int xc_off = 2 * (YT*48) + (yloc + 2) * 48 + w;   // own voxel in tile

    // ---- Phase 3: channel loop — tile-sampled gathers + FFMA2 mix ----
    unsigned long long acc[16];
    #pragma unroll
    for (int j = 0; j < 16; j++) acc[j] = 0ull;

    #pragma unroll 1
    for (int c = 0; c < CCH; c++) {
        const float* __restrict__ T = s_T + (c & 1) * TILE_N;

        // prefetch next channel's tile into the other buffer
        if (c + 1 < CCH) {
            const float* __restrict__ bn = xn + (c + 1) * DHW;
            float* __restrict__ Tn = s_T + ((c + 1) & 1) * TILE_N;
            for (int j = tid; j < TILE_N; j += TBLK) {
                int row = j / 48;
                int xx  = j - row * 48;
                int zt  = row / YT;
                int yt  = row - zt * YT;
                int zi  = min(max(z0 - 2 + zt, 0), DD - 1);
                int yi  = min(max(y0 - 2 + yt, 0), HHH - 1);
                Tn[j] = bn[zi * HW + yi * WWW + xx];
            }
        }

        float xc = T[xc_off];

        float sv[6];
        #pragma unroll
        for (int si = 0; si < 6; si++) {
            const float* pp = T + tb[si];
            const float* pz = pp + oz[si];
            float v000 = pp[0],       v001 = pp[ox[si]];
            float v010 = pp[oy[si]],  v011 = pp[oy[si] + ox[si]];
            float v100 = pz[0],       v101 = pz[ox[si]];
            float v110 = pz[oy[si]],  v111 = pz[oy[si] + ox[si]];
            float c00 = v000 + fx[si] * (v001 - v000);
            float c01 = v010 + fx[si] * (v011 - v010);
            float c10 = v100 + fx[si] * (v101 - v100);
            float c11 = v110 + fx[si] * (v111 - v110);
            float c0  = c00 + fy[si] * (c01 - c00);
            float c1  = c10 + fy[si] * (c11 - c10);
            sv[si] = c0 + fz[si] * (c1 - c0);
        }

        float s0 = sv[0] + sv[1], m0 = sv[0] - sv[1];
        float s1 = sv[2] + sv[3], m1 = sv[2] - sv[3];
        float s2 = sv[4] + sv[5], m2 = sv[4] - sv[5];

        float tv[8];
        tv[0] = cx * xc;
        tv[1] = cA[0] * s0;
        tv[2] = cA[1] * s1;
        tv[3] = cA[2] * s2;
        tv[4] = cG[0]*m0 + cG[1]*m1 + cG[2]*m2;
        tv[5] = cG[3]*m0 + cG[4]*m1 + cG[5]*m2;
        tv[6] = cG[6]*m0 + cG[7]*m1 + cG[8]*m2;
        tv[7] = cLs[0]*s0 + cLs[1]*s1 + cLs[2]*s2 + cLx * xc;

        #pragma unroll
        for (int t = 0; t < 8; t++) {
            unsigned long long v2 = pack2(tv[t]);
            const ulonglong2* wrow = (const ulonglong2*)(s_WT + (t*CCH + c)*CCH);
            #pragma unroll
            for (int j = 0; j < 8; j++) {
                ulonglong2 q = wrow[j];
                ffma2(acc[2*j+0], q.x, v2);
                ffma2(acc[2*j+1], q.y, v2);
            }
        }

        __syncthreads();   // next tile filled AND this tile fully consumed
    }

    // ---- Phase 4: out = x + delta + b_mix ----
    float* __restrict__ on = out + (size_t)n * CCH * DHW;
    #pragma unroll
    for (int j = 0; j < 16; j++) {
        float2 dv = unpack2(acc[j]);
        int o0 = 2*j, o1 = 2*j + 1;
        on[o0*DHW + zyx] = xn[o0*DHW + zyx] + dv.x + s_bmix[o0];
        on[o1*DHW + zyx] = xn[o1*DHW + zyx] + dv.y + s_bmix[o1];
    }
}

extern "C" void kernel_launch(void* const* d_in, const int* in_sizes, int n_in,
                              void* d_out, int out_size)
{
    const float* x       = (const float*)d_in[0];
    const float* w_field = (const float*)d_in[1];
    const float* b_field = (const float*)d_in[2];
    const float* gates   = (const float*)d_in[3];
    const float* w_mix   = (const float*)d_in[4];
    const float* b_mix   = (const float*)d_in[5];
    float* out = (float*)d_out;

    (void)cudaFuncSetAttribute(geo_sample3d_kernel,
                               cudaFuncAttributeMaxDynamicSharedMemorySize, SMEM_DYN);

    prep_WT_kernel<<<32, 256>>>(w_mix);

    int total_vox = in_sizes[0] / CCH;                    // 221184
    int blocks = total_vox / TBLK;                        // 1152 (exact)
    geo_sample3d_kernel<<<blocks, TBLK, SMEM_DYN>>>(x, w_field, b_field, gates,
                                                    b_mix, out);
}

// round 11
// speedup vs baseline: 2.1154x; 2.1154x over previous
#include <cuda_runtime.h>
#include <cstdint>

#define CCH 32
#define DD 48
#define HHH 48
#define WWW 48
#define HW (HHH*WWW)           // 2304
#define DHW (DD*HHH*WWW)       // 110592
#define EPSf 1e-6f
#define THREADS 256

// Pre-transposed mix weights: g_WT[m*32 + o] = w_mix[o*256 + m]
__device__ float g_WT[256 * 32];

__global__ void prep_WT_kernel(const float* __restrict__ w_mix) {
    int i = blockIdx.x * 256 + threadIdx.x;
    if (i < 256 * 32) {
        int m = i >> 5, o = i & 31;
        g_WT[m * 32 + o] = w_mix[o * 256 + m];
    }
}

// packed fp32x2 helpers
__device__ __forceinline__ void ffma2(unsigned long long &acc, unsigned long long w, unsigned long long v) {
    asm("fma.rn.f32x2 %0, %1, %2, %0;" : "+l"(acc) : "l"(w), "l"(v));
}
__device__ __forceinline__ unsigned long long pack2(float a) {
    unsigned long long r; asm("mov.b64 %0, {%1, %1};" : "=l"(r) : "f"(a)); return r;
}
__device__ __forceinline__ float2 unpack2(unsigned long long a) {
    float2 f; asm("mov.b64 {%0, %1}, %2;" : "=f"(f.x), "=f"(f.y) : "l"(a)); return f;
}

__device__ __forceinline__ float reflectf(float t, float size) {
    float c = fabsf(t + 0.5f);
    float m = fmodf(c, 2.0f * size);
    return fminf(m, 2.0f * size - m) - 0.5f;
}

// Dynamic shared layout (16B aligned):
//   [0)      s_WT  256*32 floats (32 KB), [m][o]
//   [32768)  s_S   8 warps * 2 bufs * 16 slots * 32 lanes floats (32 KB)
//   [65536)  s_wf  12*32 floats
//   [67072)  s_bf  16 floats
//   [67136)  s_bmix 32 floats
//   [67264)  s_sg  8 floats
#define OFF_WT   0
#define OFF_S    32768
#define OFF_WF   65536
#define OFF_BF   67072
#define OFF_BMIX 67136
#define OFF_SG   67264
#define SMEM_DYN 67296

__global__ __launch_bounds__(THREADS)
void geo_sample3d_kernel(const float* __restrict__ x,
                         const float* __restrict__ w_field,
                         const float* __restrict__ b_field,
                         const float* __restrict__ gates,
                         const float* __restrict__ b_mix,
                         float* __restrict__ out)
{
    extern __shared__ __align__(16) char dsm[];
    float* s_WT   = (float*)(dsm + OFF_WT);
    float* s_wf   = (float*)(dsm + OFF_WF);
    float* s_bf   = (float*)(dsm + OFF_BF);
    float* s_bmix = (float*)(dsm + OFF_BMIX);
    float* s_sg   = (float*)(dsm + OFF_SG);

    const int tid  = threadIdx.x;
    const int lane = tid & 31;
    const int wrp  = tid >> 5;
    float* warpS = (float*)(dsm + OFF_S) + wrp * 1024;   // 2 bufs * 512 floats

    #pragma unroll 4
    for (int i = tid; i < 256 * 32; i += THREADS) s_WT[i] = g_WT[i];
    for (int i = tid; i < 12 * CCH; i += THREADS) s_wf[i] = w_field[i];
    if (tid < 12)  s_bf[tid]   = b_field[tid];
    if (tid < CCH) s_bmix[tid] = b_mix[tid];
    if (tid < 8)   s_sg[tid]   = 1.0f / (1.0f + expf(-gates[tid]));
    __syncthreads();

    const int idx = blockIdx.x * THREADS + tid;   // total_vox = 864*256 exactly

    const int n   = idx / DHW;
    const int zyx = idx - n * DHW;
    const int z   = zyx / HW;
    const int r2i = zyx - z * HW;
    const int y   = r2i / WWW;
    const int w   = r2i - y * WWW;

    const float* __restrict__ xn = x + (size_t)n * CCH * DHW;

    // ---- Phase 1: field conv f[12] ----
    float f[12];
    #pragma unroll
    for (int o = 0; o < 12; o++) f[o] = s_bf[o];
    #pragma unroll 4
    for (int c = 0; c < CCH; c++) {
        float xc = xn[c * DHW + zyx];
        #pragma unroll
        for (int o = 0; o < 12; o++) f[o] = fmaf(s_wf[o * CCH + c], xc, f[o]);
    }

    // ---- Phase 2: geometry + folded token coefficients ----
    int   ib[6], ox[6], oy[6], oz[6];
    float fx[6], fy[6], fz[6];
    float cA[3], cG[9], cLs[3];
    float sumIr2 = 0.0f;

    const float gx0 = (w + 0.5f) * (2.0f / WWW) - 1.0f;
    const float gy0 = (y + 0.5f) * (2.0f / HHH) - 1.0f;
    const float gz0 = (z + 0.5f) * (2.0f / DD)  - 1.0f;

    #pragma unroll
    for (int k = 0; k < 3; k++) {
        float vx = f[4*k+0], vy = f[4*k+1], vz = f[4*k+2], fr = f[4*k+3];
        float inv_norm = rsqrtf(vx*vx + vy*vy + vz*vz + EPSf);
        float ux = vx * inv_norm, uy = vy * inv_norm, uz = vz * inv_norm;
        float r  = 0.5f + 1.5f / (1.0f + expf(-fr));
        float dx = 2.0f * r * ux / ((float)WWW + EPSf);
        float dy = 2.0f * r * uy / ((float)HHH + EPSf);
        float dz = 2.0f * r * uz / ((float)DD  + EPSf);
        float invr = 1.0f / (r + EPSf);
        float ir2  = invr * invr;
        sumIr2 += ir2;

        cA[k]     = 0.5f * s_sg[1+k];
        cG[0*3+k] = s_sg[4] * 0.5f * invr * ux;
        cG[1*3+k] = s_sg[5] * 0.5f * invr * uy;
        cG[2*3+k] = s_sg[6] * 0.5f * invr * uz;
        cLs[k]    = s_sg[7] * (1.0f/3.0f) * ir2;

        #pragma unroll
        for (int s2 = 0; s2 < 2; s2++) {
            float sgn = s2 ? -1.0f : 1.0f;
            int   si  = 2*k + s2;
            float txu = ((gx0 + sgn*dx + 1.0f) * (float)WWW - 1.0f) * 0.5f;
            float tyu = ((gy0 + sgn*dy + 1.0f) * (float)HHH - 1.0f) * 0.5f;
            float tzu = ((gz0 + sgn*dz + 1.0f) * (float)DD  - 1.0f) * 0.5f;
            float ixs = reflectf(txu, (float)WWW);
            float iys = reflectf(tyu, (float)HHH);
            float izs = reflectf(tzu, (float)DD);

            float x0f = floorf(ixs), y0f = floorf(iys), z0f = floorf(izs);
            fx[si] = ixs - x0f;  fy[si] = iys - y0f;  fz[si] = izs - z0f;

            int x0i = (int)x0f; x0i = max(0, min(x0i, WWW-1)); int x1i = min(x0i+1, WWW-1);
            int y0i = (int)y0f; y0i = max(0, min(y0i, HHH-1)); int y1i = min(y0i+1, HHH-1);
            int z0i = (int)z0f; z0i = max(0, min(z0i, DD-1));  int z1i = min(z0i+1, DD-1);

            ib[si] = z0i * HW + y0i * WWW + x0i;
            ox[si] = x1i - x0i;
            oy[si] = (y1i - y0i) * WWW;
            oz[si] = (z1i - z0i) * HW;
        }
    }

    const float cLx = -s_sg[7] * (2.0f/3.0f) * sumIr2;
    const float cx  = s_sg[0];

    // ---- Phase 3: per channel-pair: gather tokens -> warp stage -> warp GEMM ----
    const int voxg = lane >> 2;    // 0..7 : 4-voxel group within warp
    const int outg = lane & 3;     // 0..3 : 8-output group

    unsigned long long acc[16];    // [v 0..3][output pair j 0..3]
    #pragma unroll
    for (int j = 0; j < 16; j++) acc[j] = 0ull;

    #pragma unroll 1
    for (int p = 0; p < 16; p++) {
        float tv[16];
        #pragma unroll
        for (int half = 0; half < 2; half++) {
            const int c = 2*p + half;
            const float* __restrict__ bc = xn + c * DHW;
            float xc = bc[zyx];

            float sv[6];
            #pragma unroll
            for (int si = 0; si < 6; si++) {
                const float* pp = bc + ib[si];
                const float* pz = pp + oz[si];
                float v000 = pp[0],       v001 = pp[ox[si]];
                float v010 = pp[oy[si]],  v011 = pp[oy[si] + ox[si]];
                float v100 = pz[0],       v101 = pz[ox[si]];
                float v110 = pz[oy[si]],  v111 = pz[oy[si] + ox[si]];
                float c00 = v000 + fx[si] * (v001 - v000);
                float c01 = v010 + fx[si] * (v011 - v010);
                float c10 = v100 + fx[si] * (v101 - v100);
                float c11 = v110 + fx[si] * (v111 - v110);
                float c0  = c00 + fy[si] * (c01 - c00);
                float c1  = c10 + fy[si] * (c11 - c10);
                sv[si] = c0 + fz[si] * (c1 - c0);
            }

            float s0 = sv[0] + sv[1], m0 = sv[0] - sv[1];
            float s1 = sv[2] + sv[3], m1 = sv[2] - sv[3];
            float s2 = sv[4] + sv[5], m2 = sv[4] - sv[5];

            // slot s = t*2 + half
            tv[0*2+half] = cx * xc;
            tv[1*2+half] = cA[0] * s0;
            tv[2*2+half] = cA[1] * s1;
            tv[3*2+half] = cA[2] * s2;
            tv[4*2+half] = cG[0]*m0 + cG[1]*m1 + cG[2]*m2;
            tv[5*2+half] = cG[3]*m0 + cG[4]*m1 + cG[5]*m2;
            tv[6*2+half] = cG[6]*m0 + cG[7]*m1 + cG[8]*m2;
            tv[7*2+half] = cLs[0]*s0 + cLs[1]*s1 + cLs[2]*s2 + cLx * xc;
        }

        // warp-private double-buffered stage; safe with ONE syncwarp/iter:
        // reads of buf b at iter p and the next writes of buf b (iter p+2)
        // are separated by syncwarp(p+1) in every lane's program order.
        float* Sbuf = warpS + (p & 1) * 512;
        #pragma unroll
        for (int s = 0; s < 16; s++) Sbuf[s * 32 + lane] = tv[s];
        __syncwarp();

        // consume: K=16 rows; lane tile 4 voxels x 8 outputs
        #pragma unroll
        for (int s = 0; s < 16; s++) {
            const int t    = s >> 1;
            const int half = s & 1;
            const float* wb = s_WT + ((t*32 + 2*p + half) << 5) + (outg << 3);
            ulonglong2 q0 = *(const ulonglong2*)wb;         // outputs 0..3 of my 8
            ulonglong2 q1 = *(const ulonglong2*)(wb + 4);   // outputs 4..7
            const float4 av = *(const float4*)(Sbuf + s * 32 + (voxg << 2));
            unsigned long long a0 = pack2(av.x), a1 = pack2(av.y),
                               a2 = pack2(av.z), a3 = pack2(av.w);
            ffma2(acc[0],  q0.x, a0); ffma2(acc[1],  q0.y, a0);
            ffma2(acc[2],  q1.x, a0); ffma2(acc[3],  q1.y, a0);
            ffma2(acc[4],  q0.x, a1); ffma2(acc[5],  q0.y, a1);
            ffma2(acc[6],  q1.x, a1); ffma2(acc[7],  q1.y, a1);
            ffma2(acc[8],  q0.x, a2); ffma2(acc[9],  q0.y, a2);
            ffma2(acc[10], q1.x, a2); ffma2(acc[11], q1.y, a2);
            ffma2(acc[12], q0.x, a3); ffma2(acc[13], q0.y, a3);
            ffma2(acc[14], q1.x, a3); ffma2(acc[15], q1.y, a3);
        }
    }

    // ---- Phase 4: epilogue — my tile = 4 consecutive voxels x 8 outputs ----
    const int vt   = blockIdx.x * THREADS + wrp * 32 + (voxg << 2);
    const int n2   = vt / DHW;
    const int zyx2 = vt - n2 * DHW;
    const float* __restrict__ xn2 = x + (size_t)n2 * CCH * DHW;
    float* __restrict__ on2       = out + (size_t)n2 * CCH * DHW;
    #pragma unroll
    for (int jj = 0; jj < 4; jj++) {
        int o0 = (outg << 3) + 2*jj;
        float2 d0 = unpack2(acc[0*4 + jj]);   // voxel vt+0, outputs (o0, o0+1)
        float2 d1 = unpack2(acc[1*4 + jj]);
        float2 d2 = unpack2(acc[2*4 + jj]);
        float2 d3 = unpack2(acc[3*4 + jj]);
        {
            float4 xv = *(const float4*)(xn2 + (size_t)o0 * DHW + zyx2);
            float b = s_bmix[o0];
            float4 ov = make_float4(xv.x + d0.x + b, xv.y + d1.x + b,
                                    xv.z + d2.x + b, xv.w + d3.x + b);
            *(float4*)(on2 + (size_t)o0 * DHW + zyx2) = ov;
        }
        {
            int o1 = o0 + 1;
            float4 xv = *(const float4*)(xn2 + (size_t)o1 * DHW + zyx2);
            float b = s_bmix[o1];
            float4 ov = make_float4(xv.x + d0.y + b, xv.y + d1.y + b,
                                    xv.z + d2.y + b, xv.w + d3.y + b);
            *(float4*)(on2 + (size_t)o1 * DHW + zyx2) = ov;
        }
    }
}

extern "C" void kernel_launch(void* const* d_in, const int* in_sizes, int n_in,
                              void* d_out, int out_size)
{
    const float* x       = (const float*)d_in[0];
    const float* w_field = (const float*)d_in[1];
    const float* b_field = (const float*)d_in[2];
    const float* gates   = (const float*)d_in[3];
    const float* w_mix   = (const float*)d_in[4];
    const float* b_mix   = (const float*)d_in[5];
    float* out = (float*)d_out;

    (void)cudaFuncSetAttribute(geo_sample3d_kernel,
                               cudaFuncAttributeMaxDynamicSharedMemorySize, SMEM_DYN);

    prep_WT_kernel<<<32, 256>>>(w_mix);

    int total_vox = in_sizes[0] / CCH;                 // 221184
    int blocks = total_vox / THREADS;                  // 864 (exact)
    geo_sample3d_kernel<<<blocks, THREADS, SMEM_DYN>>>(x, w_field, b_field, gates,
                                                       b_mix, out);
}

// round 12
// speedup vs baseline: 2.6927x; 1.2729x over previous
#include <cuda_runtime.h>
#include <cuda_fp16.h>
#include <cstdint>

#define CCH 32
#define DD 48
#define HHH 48
#define WWW 48
#define HW (HHH*WWW)           // 2304
#define DHW (DD*HHH*WWW)       // 110592
#define NTOT (2*CCH*DHW)       // 7077888 elements
#define EPSf 1e-6f
#define THREADS 256

// Pre-transposed mix weights: g_WT[m*32 + o] = w_mix[o*256 + m]
__device__ float g_WT[256 * 32];
// Paired-corner half2 image: g_x2[i] = (x[i], x[i with x-coord+1 clamped])
__device__ half2 g_x2[NTOT];

__global__ void prep_WT_kernel(const float* __restrict__ w_mix) {
    int i = blockIdx.x * 256 + threadIdx.x;
    if (i < 256 * 32) {
        int m = i >> 5, o = i & 31;
        g_WT[m * 32 + o] = w_mix[o * 256 + m];
    }
}

__global__ __launch_bounds__(256) void prep_x2_kernel(const float* __restrict__ x) {
    int i = blockIdx.x * 256 + threadIdx.x;
    if (i < NTOT) {
        int xx = i % WWW;
        float a = x[i];
        float b = (xx < WWW - 1) ? x[i + 1] : a;
        g_x2[i] = __floats2half2_rn(a, b);
    }
}

// packed fp32x2 helpers
__device__ __forceinline__ void ffma2(unsigned long long &acc, unsigned long long w, unsigned long long v) {
    asm("fma.rn.f32x2 %0, %1, %2, %0;" : "+l"(acc) : "l"(w), "l"(v));
}
__device__ __forceinline__ unsigned long long pack2(float a) {
    unsigned long long r; asm("mov.b64 %0, {%1, %1};" : "=l"(r) : "f"(a)); return r;
}
__device__ __forceinline__ float2 unpack2(unsigned long long a) {
    float2 f; asm("mov.b64 {%0, %1}, %2;" : "=f"(f.x), "=f"(f.y) : "l"(a)); return f;
}

__device__ __forceinline__ float reflectf(float t, float size) {
    float c = fabsf(t + 0.5f);
    float m = fmodf(c, 2.0f * size);
    return fminf(m, 2.0f * size - m) - 0.5f;
}

// Dynamic shared layout (16B aligned):
#define OFF_WT   0
#define OFF_S    32768
#define OFF_WF   65536
#define OFF_BF   67072
#define OFF_BMIX 67136
#define OFF_SG   67264
#define SMEM_DYN 67296

__global__ __launch_bounds__(THREADS)
void geo_sample3d_kernel(const float* __restrict__ x,
                         const float* __restrict__ w_field,
                         const float* __restrict__ b_field,
                         const float* __restrict__ gates,
                         const float* __restrict__ b_mix,
                         float* __restrict__ out)
{
    extern __shared__ __align__(16) char dsm[];
    float* s_WT   = (float*)(dsm + OFF_WT);
    float* s_wf   = (float*)(dsm + OFF_WF);
    float* s_bf   = (float*)(dsm + OFF_BF);
    float* s_bmix = (float*)(dsm + OFF_BMIX);
    float* s_sg   = (float*)(dsm + OFF_SG);

    const int tid  = threadIdx.x;
    const int lane = tid & 31;
    const int wrp  = tid >> 5;
    float* warpS = (float*)(dsm + OFF_S) + wrp * 1024;   // 2 bufs * 512 floats

    #pragma unroll 4
    for (int i = tid; i < 256 * 32; i += THREADS) s_WT[i] = g_WT[i];
    for (int i = tid; i < 12 * CCH; i += THREADS) s_wf[i] = w_field[i];
    if (tid < 12)  s_bf[tid]   = b_field[tid];
    if (tid < CCH) s_bmix[tid] = b_mix[tid];
    if (tid < 8)   s_sg[tid]   = 1.0f / (1.0f + expf(-gates[tid]));
    __syncthreads();

    const int idx = blockIdx.x * THREADS + tid;   // total_vox = 864*256 exactly

    const int n   = idx / DHW;
    const int zyx = idx - n * DHW;
    const int z   = zyx / HW;
    const int r2i = zyx - z * HW;
    const int y   = r2i / WWW;
    const int w   = r2i - y * WWW;

    const float* __restrict__ xn  = x + (size_t)n * CCH * DHW;
    const half2* __restrict__ x2n = g_x2 + (size_t)n * CCH * DHW;

    // ---- Phase 1: field conv f[12] ----
    float f[12];
    #pragma unroll
    for (int o = 0; o < 12; o++) f[o] = s_bf[o];
    #pragma unroll 4
    for (int c = 0; c < CCH; c++) {
        float xc = xn[c * DHW + zyx];
        #pragma unroll
        for (int o = 0; o < 12; o++) f[o] = fmaf(s_wf[o * CCH + c], xc, f[o]);
    }

    // ---- Phase 2: geometry + folded token coefficients ----
    int   ib[6], oy[6], oz[6];
    float fx[6], fy[6], fz[6];
    float cA[3], cG[9], cLs[3];
    float sumIr2 = 0.0f;

    const float gx0 = (w + 0.5f) * (2.0f / WWW) - 1.0f;
    const float gy0 = (y + 0.5f) * (2.0f / HHH) - 1.0f;
    const float gz0 = (z + 0.5f) * (2.0f / DD)  - 1.0f;

    #pragma unroll
    for (int k = 0; k < 3; k++) {
        float vx = f[4*k+0], vy = f[4*k+1], vz = f[4*k+2], fr = f[4*k+3];
        float inv_norm = rsqrtf(vx*vx + vy*vy + vz*vz + EPSf);
        float ux = vx * inv_norm, uy = vy * inv_norm, uz = vz * inv_norm;
        float r  = 0.5f + 1.5f / (1.0f + expf(-fr));
        float dx = 2.0f * r * ux / ((float)WWW + EPSf);
        float dy = 2.0f * r * uy / ((float)HHH + EPSf);
        float dz = 2.0f * r * uz / ((float)DD  + EPSf);
        float invr = 1.0f / (r + EPSf);
        float ir2  = invr * invr;
        sumIr2 += ir2;

        cA[k]     = 0.5f * s_sg[1+k];
        cG[0*3+k] = s_sg[4] * 0.5f * invr * ux;
        cG[1*3+k] = s_sg[5] * 0.5f * invr * uy;
        cG[2*3+k] = s_sg[6] * 0.5f * invr * uz;
        cLs[k]    = s_sg[7] * (1.0f/3.0f) * ir2;

        #pragma unroll
        for (int s2 = 0; s2 < 2; s2++) {
            float sgn = s2 ? -1.0f : 1.0f;
            int   si  = 2*k + s2;
            float txu = ((gx0 + sgn*dx + 1.0f) * (float)WWW - 1.0f) * 0.5f;
            float tyu = ((gy0 + sgn*dy + 1.0f) * (float)HHH - 1.0f) * 0.5f;
            float tzu = ((gz0 + sgn*dz + 1.0f) * (float)DD  - 1.0f) * 0.5f;
            float ixs = reflectf(txu, (float)WWW);
            float iys = reflectf(tyu, (float)HHH);
            float izs = reflectf(tzu, (float)DD);

            float x0f = floorf(ixs), y0f = floorf(iys), z0f = floorf(izs);
            fx[si] = ixs - x0f;  fy[si] = iys - y0f;  fz[si] = izs - z0f;

            int x0i = (int)x0f; x0i = max(0, min(x0i, WWW-1));
            int y0i = (int)y0f; y0i = max(0, min(y0i, HHH-1)); int y1i = min(y0i+1, HHH-1);
            int z0i = (int)z0f; z0i = max(0, min(z0i, DD-1));  int z1i = min(z0i+1, DD-1);

            ib[si] = z0i * HW + y0i * WWW + x0i;      // x-pair (x0, x0+1 clamped) baked into g_x2
            oy[si] = (y1i - y0i) * WWW;
            oz[si] = (z1i - z0i) * HW;
        }
    }

    const float cLx = -s_sg[7] * (2.0f/3.0f) * sumIr2;
    const float cx  = s_sg[0];

    // ---- Phase 3: per channel-pair: paired-corner gathers -> warp stage -> warp GEMM ----
    const int voxg = lane >> 2;    // 0..7 : 4-voxel group within warp
    const int outg = lane & 3;     // 0..3 : 8-output group

    unsigned long long acc[16];
    #pragma unroll
    for (int j = 0; j < 16; j++) acc[j] = 0ull;

    #pragma unroll 1
    for (int p = 0; p < 16; p++) {
        float tv[16];
        #pragma unroll
        for (int half_ = 0; half_ < 2; half_++) {
            const int c = 2*p + half_;
            const half2* __restrict__ b2 = x2n + c * DHW;
            float xc = xn[c * DHW + zyx];

            float sv[6];
            #pragma unroll
            for (int si = 0; si < 6; si++) {
                const half2* pp = b2 + ib[si];
                const half2* pz = pp + oz[si];
                float2 v00 = __half22float2(pp[0]);        // (v000, v001)
                float2 v01 = __half22float2(pp[oy[si]]);   // (v010, v011)
                float2 v10 = __half22float2(pz[0]);        // (v100, v101)
                float2 v11 = __half22float2(pz[oy[si]]);   // (v110, v111)
                float c00 = v00.x + fx[si] * (v00.y - v00.x);
                float c01 = v01.x + fx[si] * (v01.y - v01.x);
                float c10 = v10.x + fx[si] * (v10.y - v10.x);
                float c11 = v11.x + fx[si] * (v11.y - v11.x);
                float c0  = c00 + fy[si] * (c01 - c00);
                float c1  = c10 + fy[si] * (c11 - c10);
                sv[si] = c0 + fz[si] * (c1 - c0);
            }

            float s0 = sv[0] + sv[1], m0 = sv[0] - sv[1];
            float s1 = sv[2] + sv[3], m1 = sv[2] - sv[3];
            float s2 = sv[4] + sv[5], m2 = sv[4] - sv[5];

            tv[0*2+half_] = cx * xc;
            tv[1*2+half_] = cA[0] * s0;
            tv[2*2+half_] = cA[1] * s1;
            tv[3*2+half_] = cA[2] * s2;
            tv[4*2+half_] = cG[0]*m0 + cG[1]*m1 + cG[2]*m2;
            tv[5*2+half_] = cG[3]*m0 + cG[4]*m1 + cG[5]*m2;
            tv[6*2+half_] = cG[6]*m0 + cG[7]*m1 + cG[8]*m2;
            tv[7*2+half_] = cLs[0]*s0 + cLs[1]*s1 + cLs[2]*s2 + cLx * xc;
        }

        // warp-private double-buffered stage; one syncwarp per iteration
        float* Sbuf = warpS + (p & 1) * 512;
        #pragma unroll
        for (int s = 0; s < 16; s++) Sbuf[s * 32 + lane] = tv[s];
        __syncwarp();

        #pragma unroll
        for (int s = 0; s < 16; s++) {
            const int t     = s >> 1;
            const int half_ = s & 1;
            const float* wb = s_WT + ((t*32 + 2*p + half_) << 5) + (outg << 3);
            ulonglong2 q0 = *(const ulonglong2*)wb;
            ulonglong2 q1 = *(const ulonglong2*)(wb + 4);
            const float4 av = *(const float4*)(Sbuf + s * 32 + (voxg << 2));
            unsigned long long a0 = pack2(av.x), a1 = pack2(av.y),
                               a2 = pack2(av.z), a3 = pack2(av.w);
            ffma2(acc[0],  q0.x, a0); ffma2(acc[1],  q0.y, a0);
            ffma2(acc[2],  q1.x, a0); ffma2(acc[3],  q1.y, a0);
            ffma2(acc[4],  q0.x, a1); ffma2(acc[5],  q0.y, a1);
            ffma2(acc[6],  q1.x, a1); ffma2(acc[7],  q1.y, a1);
            ffma2(acc[8],  q0.x, a2); ffma2(acc[9],  q0.y, a2);
            ffma2(acc[10], q1.x, a2); ffma2(acc[11], q1.y, a2);
            ffma2(acc[12], q0.x, a3); ffma2(acc[13], q0.y, a3);
            ffma2(acc[14], q1.x, a3); ffma2(acc[15], q1.y, a3);
        }
    }

    // ---- Phase 4: epilogue — my tile = 4 consecutive voxels x 8 outputs ----
    const int vt   = blockIdx.x * THREADS + wrp * 32 + (voxg << 2);
    const int n2   = vt / DHW;
    const int zyx2 = vt - n2 * DHW;
    const float* __restrict__ xn2 = x + (size_t)n2 * CCH * DHW;
    float* __restrict__ on2       = out + (size_t)n2 * CCH * DHW;
    #pragma unroll
    for (int jj = 0; jj < 4; jj++) {
        int o0 = (outg << 3) + 2*jj;
        float2 d0 = unpack2(acc[0*4 + jj]);
        float2 d1 = unpack2(acc[1*4 + jj]);
        float2 d2 = unpack2(acc[2*4 + jj]);
        float2 d3 = unpack2(acc[3*4 + jj]);
        {
            float4 xv = *(const float4*)(xn2 + (size_t)o0 * DHW + zyx2);
            float b = s_bmix[o0];
            float4 ov = make_float4(xv.x + d0.x + b, xv.y + d1.x + b,
                                    xv.z + d2.x + b, xv.w + d3.x + b);
            *(float4*)(on2 + (size_t)o0 * DHW + zyx2) = ov;
        }
        {
            int o1 = o0 + 1;
            float4 xv = *(const float4*)(xn2 + (size_t)o1 * DHW + zyx2);
            float b = s_bmix[o1];
            float4 ov = make_float4(xv.x + d0.y + b, xv.y + d1.y + b,
                                    xv.z + d2.y + b, xv.w + d3.y + b);
            *(float4*)(on2 + (size_t)o1 * DHW + zyx2) = ov;
        }
    }
}

extern "C" void kernel_launch(void* const* d_in, const int* in_sizes, int n_in,
                              void* d_out, int out_size)
{
    const float* x       = (const float*)d_in[0];
    const float* w_field = (const float*)d_in[1];
    const float* b_field = (const float*)d_in[2];
    const float* gates   = (const float*)d_in[3];
    const float* w_mix   = (const float*)d_in[4];
    const float* b_mix   = (const float*)d_in[5];
    float* out = (float*)d_out;

    (void)cudaFuncSetAttribute(geo_sample3d_kernel,
                               cudaFuncAttributeMaxDynamicSharedMemorySize, SMEM_DYN);

    prep_WT_kernel<<<32, 256>>>(w_mix);
    prep_x2_kernel<<<(NTOT + 255) / 256, 256>>>(x);

    int total_vox = in_sizes[0] / CCH;                 // 221184
    int blocks = total_vox / THREADS;                  // 864 (exact)
    geo_sample3d_kernel<<<blocks, THREADS, SMEM_DYN>>>(x, w_field, b_field, gates,
                                                       b_mix, out);
}